// round 10
// baseline (speedup 1.0000x reference)
#include <cuda_runtime.h>
#include <cuda_fp16.h>

#define N_NODES 2000
#define N_EDGES 32000
#define NG      320      // B*T graphs
#define OUTF    8
#define HID     24
#define BB      16
#define TT      20
#define STRIP   4
#define NEG_SLOPE 0.2f

// ---------------- scratch (device globals; no allocs allowed) ----------------
__device__ __half  g_wTh[(size_t)N_EDGES * NG]; // [csr_pos][320]  CSR-ordered, fp16
__device__ float   g_xT[(size_t)N_NODES * NG];  // [node][320]
__device__ int     g_srcc[N_EDGES];             // CSR slot -> src node
__device__ int     g_rowptr[N_NODES + 1];
__device__ int     g_deg[N_NODES];              // zeroed by K1 scan-block each call
__device__ int     g_cur[N_NODES];              // zeroed by K1 scan-block each call
__device__ float2  g_S[NG];                     // zeroed by K1 scan-block each call
__device__ unsigned int g_cnt1 = 0;             // K1 fan-in counter
__device__ float   g_M[20 * HID];               // composed head: fcc_w @ fc_w [20][24]
__device__ float   g_bias2[20];                 // fcc_w @ fc_b + fcc_b

// =====================================================================
// K1: x-transpose + degree histogram + head composition (independent);
//     LAST block (fan-in) does: scan deg->rowptr, zero deg/cur/S, reset cnt.
//   blocks [0,630):   x-transpose tiles (63 node-tiles x 10 graph-tiles)
//   blocks [630,755): histogram (125 x 256 = 32000 edges)
//   block  755:       M = fcc_w @ fc_w, bias2 (no dependencies)
// =====================================================================
__global__ void xtrans_hist_scan_kernel(const float* __restrict__ xin,
                                        const int* __restrict__ dst,
                                        const float* __restrict__ fc_w,
                                        const float* __restrict__ fc_b,
                                        const float* __restrict__ fcc_w,
                                        const float* __restrict__ fcc_b) {
    __shared__ float tile[32][33];
    __shared__ float s_fcw[160 * HID];           // 15 KB (M block only)
    __shared__ int ssum[256];
    __shared__ int sflag;
    int bid = blockIdx.x;
    int tid = threadIdx.x;

    if (bid < 630) {
        int tx = tid & 31, ty = tid >> 5;
        int cb = (bid % 63) * 32;            // node base
        int rb = (bid / 63) * 32;            // graph base
        #pragma unroll
        for (int i = 0; i < 32; i += 8) {
            int c = cb + tx;
            tile[ty + i][tx] = (c < N_NODES)
                ? xin[(size_t)(rb + ty + i) * N_NODES + c] : 0.0f;
        }
        __syncthreads();
        #pragma unroll
        for (int i = 0; i < 32; i += 8) {
            int c = cb + ty + i;
            if (c < N_NODES) g_xT[(size_t)c * NG + rb + tx] = tile[tx][ty + i];
        }
    } else if (bid < 755) {
        int e = (bid - 630) * 256 + tid;
        if (e < N_EDGES) atomicAdd(&g_deg[dst[e]], 1);
    } else {
        // ---- head composition ----
        for (int i = tid; i < 160 * HID; i += 256) s_fcw[i] = fc_w[i];
        __syncthreads();
        for (int idx = tid; idx < 20 * HID; idx += 256) {
            int m = idx / HID, k = idx % HID;
            float acc = 0.f;
            #pragma unroll 8
            for (int q = 0; q < 160; q++)
                acc = fmaf(fcc_w[m * 160 + q], s_fcw[q * HID + k], acc);
            g_M[idx] = acc;
        }
        if (tid < 20) {
            float acc = fcc_b[tid];
            #pragma unroll 8
            for (int q = 0; q < 160; q++)
                acc = fmaf(fcc_w[tid * 160 + q], fc_b[q], acc);
            g_bias2[tid] = acc;
        }
    }

    __threadfence();
    __syncthreads();
    if (tid == 0)
        sflag = (atomicAdd(&g_cnt1, 1) == gridDim.x - 1) ? 1 : 0;
    __syncthreads();
    if (!sflag) return;
    __threadfence();

    int base = tid * 8;
    int v[8];
    int run = 0;
    if (tid < 250) {
        #pragma unroll
        for (int k = 0; k < 8; k++) {
            int d = g_deg[base + k];
            v[k] = run;
            run += d;
        }
    } else {
        #pragma unroll
        for (int k = 0; k < 8; k++) v[k] = 0;
    }
    ssum[tid] = run;
    __syncthreads();
    for (int off = 1; off < 256; off <<= 1) {
        int a = (tid >= off) ? ssum[tid - off] : 0;
        __syncthreads();
        ssum[tid] += a;
        __syncthreads();
    }
    int excl = ssum[tid] - run;
    if (tid < 250) {
        #pragma unroll
        for (int k = 0; k < 8; k++) {
            g_rowptr[base + k] = excl + v[k];
            g_deg[base + k] = 0;
            g_cur[base + k] = 0;
        }
    }
    if (tid == 249) g_rowptr[N_NODES] = excl + run;
    for (int i = tid; i < NG; i += 256) g_S[i] = make_float2(0.0f, 0.0f);
    if (tid == 0) g_cnt1 = 0;
}

// =====================================================================
// K2: fused scatter + CSR-permuted w-transpose (fp16, half2-packed stores).
//   Write phase: 160-thread groups store __half2 -> 640B contiguous/edge.
// =====================================================================
__global__ void __launch_bounds__(NG) scat_wtrans_kernel(
        const float* __restrict__ win,
        const int* __restrict__ src,
        const int* __restrict__ dst) {
    __shared__ float tile[NG][33];           // [g][e], 42.2 KB
    __shared__ int s_pos[32];
    int tid = threadIdx.x;
    int eb = blockIdx.x * 32;

    if (tid < 32) {
        int e = eb + tid;
        int d = dst[e];
        int p = g_rowptr[d] + atomicAdd(&g_cur[d], 1);
        s_pos[tid] = p;
        g_srcc[p] = src[e];
    }

    #pragma unroll
    for (int r = 0; r < 8; r++) {
        int idx = r * NG + tid;
        int g = idx >> 3, q = idx & 7;
        float4 vv = *(const float4*)&win[(size_t)g * N_EDGES + eb + q * 4];
        tile[g][q * 4 + 0] = vv.x;
        tile[g][q * 4 + 1] = vv.y;
        tile[g][q * 4 + 2] = vv.z;
        tile[g][q * 4 + 3] = vv.w;
    }
    __syncthreads();

    // 32 edges x 160 half2 = 5120 items; 16 iters x 320 threads.
    // threads [0,160) -> edge 2k, [160,320) -> edge 2k+1 each iter.
    #pragma unroll
    for (int it = 0; it < 16; it++) {
        int lin = it * NG + tid;             // 0..5119
        int e  = lin / 160;
        int gp = lin % 160;
        __half2 v = __floats2half2_rn(tile[2 * gp][e], tile[2 * gp + 1][e]);
        *(__half2*)&g_wTh[(size_t)s_pos[e] * NG + 2 * gp] = v;
    }
}

// =====================================================================
// K3: GAT reduction. CTA = strip of 4 nodes (500 CTAs, 320 thr), thread=graph.
// =====================================================================
__global__ void __launch_bounds__(NG) gat_kernel(const float* __restrict__ W_node,
                           const float* __restrict__ W_edge,
                           const float* __restrict__ attn_l,
                           const float* __restrict__ attn_e,
                           const float* __restrict__ attn_r) {
    int g = threadIdx.x;

    float cL = 0.f, cE = 0.f, cR = 0.f;
    #pragma unroll
    for (int o = 0; o < OUTF; o++) {
        float wn = __ldg(&W_node[o]);
        float we = __ldg(&W_edge[o]);
        cL = fmaf(wn, __ldg(&attn_l[o]), cL);
        cR = fmaf(wn, __ldg(&attn_r[o]), cR);
        cE = fmaf(we, __ldg(&attn_e[o]), cE);
    }

    int n0 = blockIdx.x * STRIP;
    float acc1 = 0.f, acc2 = 0.f;

    #pragma unroll
    for (int nn = 0; nn < STRIP; nn++) {
        int node = n0 + nn;
        float xd = g_xT[(size_t)node * NG + g];
        float based = cR * xd;
        int s0 = g_rowptr[node], s1 = g_rowptr[node + 1];

        float den = 0.f, T1 = 0.f, T2 = 0.f;
        int j = s0;
        for (; j + 4 <= s1; j += 4) {
            int sa = g_srcc[j];
            int sb = g_srcc[j + 1];
            int sc = g_srcc[j + 2];
            int sd = g_srcc[j + 3];
            float w0 = __half2float(g_wTh[(size_t)(j    ) * NG + g]);
            float w1 = __half2float(g_wTh[(size_t)(j + 1) * NG + g]);
            float w2 = __half2float(g_wTh[(size_t)(j + 2) * NG + g]);
            float w3 = __half2float(g_wTh[(size_t)(j + 3) * NG + g]);
            float x0 = g_xT[(size_t)sa * NG + g];
            float x1 = g_xT[(size_t)sb * NG + g];
            float x2 = g_xT[(size_t)sc * NG + g];
            float x3 = g_xT[(size_t)sd * NG + g];

            float v0 = fmaf(cL, x0, fmaf(cE, w0, based));
            float v1 = fmaf(cL, x1, fmaf(cE, w1, based));
            float v2 = fmaf(cL, x2, fmaf(cE, w2, based));
            float v3 = fmaf(cL, x3, fmaf(cE, w3, based));
            v0 = fmaxf(v0, NEG_SLOPE * v0);
            v1 = fmaxf(v1, NEG_SLOPE * v1);
            v2 = fmaxf(v2, NEG_SLOPE * v2);
            v3 = fmaxf(v3, NEG_SLOPE * v3);
            float p0 = __expf(v0);
            float p1 = __expf(v1);
            float p2 = __expf(v2);
            float p3 = __expf(v3);
            den += p0; T1 = fmaf(p0, x0, T1); T2 = fmaf(p0, w0, T2);
            den += p1; T1 = fmaf(p1, x1, T1); T2 = fmaf(p1, w1, T2);
            den += p2; T1 = fmaf(p2, x2, T1); T2 = fmaf(p2, w2, T2);
            den += p3; T1 = fmaf(p3, x3, T1); T2 = fmaf(p3, w3, T2);
        }
        for (; j < s1; j++) {
            float w  = __half2float(g_wTh[(size_t)j * NG + g]);
            float xs = g_xT[(size_t)g_srcc[j] * NG + g];
            float v = fmaf(cL, xs, fmaf(cE, w, based));
            v = fmaxf(v, NEG_SLOPE * v);
            float p = __expf(v);
            den += p; T1 = fmaf(p, xs, T1); T2 = fmaf(p, w, T2);
        }
        if (s1 > s0) {
            float inv = 1.0f / den;
            acc1 = fmaf(T1, inv, acc1);
            acc2 = fmaf(T2, inv, acc2);
        }
    }
    atomicAdd(&g_S[g].x, acc1);
    atomicAdd(&g_S[g].y, acc2);
}

// =====================================================================
// K4: warp-synchronous LSTM + composed head.
//   2 CTAs x 256 threads: 8 warps/SM = 2 warps per SMSP so each warp's
//   stalls are absorbed by its sibling. Warp = batch (b = blk*8 + wid).
//   Per-warp code identical to the proven R7/R9 version.
// =====================================================================
__device__ __forceinline__ float sigm(float x) { return 1.0f / (1.0f + __expf(-x)); }
__device__ __forceinline__ float tanhfast(float x) {
    float t = __expf(-2.0f * x);
    return __fdividef(1.0f - t, 1.0f + t);
}

__global__ void __launch_bounds__(256) lstm_head_kernel(
        const float* __restrict__ W_node,
        const float* __restrict__ W_edge,
        const float* __restrict__ gat_b,
        const float* __restrict__ w_ih,
        const float* __restrict__ w_hh,
        const float* __restrict__ b_ih,
        const float* __restrict__ b_hh,
        float* __restrict__ out) {
    int b = blockIdx.x * 8 + (threadIdx.x >> 5);  // batch 0..15
    int lane = threadIdx.x & 31;
    const float invN = 1.0f / N_NODES;

    // preload all timestep sums (lane t holds step t's pair)
    float s1 = 0.f, s2 = 0.f;
    if (lane < TT) { float2 S = g_S[b * TT + lane]; s1 = S.x; s2 = S.y; }

    // per-gate folded input coefficients + w_hh rows (lane j<24, gates i,f,g,o)
    float A1[4], A2[4], A3[4];
    float whh[4][HID];
    #pragma unroll
    for (int gg = 0; gg < 4; gg++) {
        A1[gg] = A2[gg] = A3[gg] = 0.f;
        #pragma unroll
        for (int j = 0; j < HID; j++) whh[gg][j] = 0.f;
    }
    if (lane < HID) {
        #pragma unroll
        for (int gg = 0; gg < 4; gg++) {
            int row = gg * HID + lane;
            float a1 = 0.f, a2 = 0.f, a3 = b_ih[row] + b_hh[row];
            #pragma unroll
            for (int o = 0; o < OUTF; o++) {
                float wv = w_ih[row * OUTF + o];
                a1 = fmaf(wv, W_node[o], a1);
                a2 = fmaf(wv, W_edge[o], a2);
                a3 = fmaf(wv, gat_b[o], a3);
            }
            A1[gg] = a1 * invN;
            A2[gg] = a2 * invN;
            A3[gg] = a3;
            #pragma unroll
            for (int j = 0; j < HID; j++) whh[gg][j] = w_hh[row * HID + j];
        }
    }

    // composed head row for this lane (lane m<20 -> out column m)
    float Mrow[HID];
    #pragma unroll
    for (int j = 0; j < HID; j++) Mrow[j] = 0.f;
    float bias2 = 0.f;
    if (lane < 20) {
        #pragma unroll
        for (int j = 0; j < HID; j++) Mrow[j] = g_M[lane * HID + j];
        bias2 = g_bias2[lane];
    }

    float h = 0.f, c = 0.f, oacc = 0.f;
    for (int t = 0; t < TT; t++) {
        float S1t = __shfl_sync(0xffffffffu, s1, t);
        float S2t = __shfl_sync(0xffffffffu, s2, t);
        float g0 = fmaf(S1t, A1[0], fmaf(S2t, A2[0], A3[0]));
        float g1 = fmaf(S1t, A1[1], fmaf(S2t, A2[1], A3[1]));
        float g2 = fmaf(S1t, A1[2], fmaf(S2t, A2[2], A3[2]));
        float g3 = fmaf(S1t, A1[3], fmaf(S2t, A2[3], A3[3]));
        if (t > 0) {
            // broadcast h_{t-1}: feeds gates of step t AND output of step t-1
            #pragma unroll
            for (int j = 0; j < HID; j++) {
                float hj = __shfl_sync(0xffffffffu, h, j);
                g0 = fmaf(whh[0][j], hj, g0);
                g1 = fmaf(whh[1][j], hj, g1);
                g2 = fmaf(whh[2][j], hj, g2);
                g3 = fmaf(whh[3][j], hj, g3);
                oacc = fmaf(Mrow[j], hj, oacc);
            }
            if (lane < 20) out[(b * TT + (t - 1)) * 20 + lane] = oacc + bias2;
            oacc = 0.f;
        }
        float gi = sigm(g0);
        float gf = sigm(g1);
        float tg = tanhfast(g2);
        float go = sigm(g3);
        c = fmaf(gf, c, gi * tg);
        h = go * tanhfast(c);
    }
    // final output (step TT-1)
    #pragma unroll
    for (int j = 0; j < HID; j++) {
        float hj = __shfl_sync(0xffffffffu, h, j);
        oacc = fmaf(Mrow[j], hj, oacc);
    }
    if (lane < 20) out[(b * TT + TT - 1) * 20 + lane] = oacc + bias2;
}

// ---------------- launch ----------------
extern "C" void kernel_launch(void* const* d_in, const int* in_sizes, int n_in,
                              void* d_out, int out_size) {
    const float* x      = (const float*)d_in[0];
    const float* ew     = (const float*)d_in[1];
    const int*   src    = (const int*)  d_in[2];
    const int*   dst    = (const int*)  d_in[3];
    const float* W_node = (const float*)d_in[4];
    const float* W_edge = (const float*)d_in[5];
    const float* attn_l = (const float*)d_in[6];
    const float* attn_e = (const float*)d_in[7];
    const float* attn_r = (const float*)d_in[8];
    const float* gat_b  = (const float*)d_in[9];
    const float* w_ih   = (const float*)d_in[10];
    const float* w_hh   = (const float*)d_in[11];
    const float* b_ih   = (const float*)d_in[12];
    const float* b_hh   = (const float*)d_in[13];
    const float* fc_w   = (const float*)d_in[14];
    const float* fc_b   = (const float*)d_in[15];
    const float* fcc_w  = (const float*)d_in[16];
    const float* fcc_b  = (const float*)d_in[17];
    float* out = (float*)d_out;

    xtrans_hist_scan_kernel<<<756, 256>>>(x, dst, fc_w, fc_b, fcc_w, fcc_b);
    scat_wtrans_kernel<<<N_EDGES / 32, NG>>>(ew, src, dst);
    gat_kernel<<<N_NODES / STRIP, NG>>>(W_node, W_edge, attn_l, attn_e, attn_r);
    lstm_head_kernel<<<2, 256>>>(W_node, W_edge, gat_b, w_ih, w_hh, b_ih, b_hh, out);
}

// round 11
// speedup vs baseline: 1.3577x; 1.3577x over previous
#include <cuda_runtime.h>
#include <cuda_fp16.h>

#define N_NODES 2000
#define N_EDGES 32000
#define NG      320      // B*T graphs
#define OUTF    8
#define HID     24
#define BB      16
#define TT      20
#define STRIP   4
#define NEG_SLOPE 0.2f

// ---------------- scratch (device globals; no allocs allowed) ----------------
__device__ __half  g_wTh[(size_t)N_EDGES * NG]; // [csr_pos][320]  CSR-ordered, fp16
__device__ float   g_xT[(size_t)N_NODES * NG];  // [node][320]
__device__ int     g_srcc[N_EDGES];             // CSR slot -> src node
__device__ int     g_rowptr[N_NODES + 1];
__device__ int     g_deg[N_NODES];              // zeroed by K1 scan-block each call
__device__ int     g_cur[N_NODES];              // zeroed by K1 scan-block each call
__device__ float2  g_S[NG];                     // zeroed by K1 scan-block each call
__device__ unsigned int g_cnt1 = 0;             // K1 fan-in counter
__device__ float   g_M[20 * HID];               // composed head: fcc_w @ fc_w [20][24]
__device__ float   g_bias2[20];                 // fcc_w @ fc_b + fcc_b

// =====================================================================
// K1: x-transpose [320][N] -> [N][320]  +  degree histogram;
//     LAST block (fan-in) does: scan deg->rowptr, zero deg/cur/S, reset cnt.
// =====================================================================
__global__ void xtrans_hist_scan_kernel(const float* __restrict__ xin,
                                        const int* __restrict__ dst) {
    __shared__ float tile[32][33];
    __shared__ int ssum[256];
    __shared__ int sflag;
    int bid = blockIdx.x;
    int tid = threadIdx.x;

    if (bid < 630) {
        int tx = tid & 31, ty = tid >> 5;
        int cb = (bid % 63) * 32;            // node base
        int rb = (bid / 63) * 32;            // graph base
        #pragma unroll
        for (int i = 0; i < 32; i += 8) {
            int c = cb + tx;
            tile[ty + i][tx] = (c < N_NODES)
                ? xin[(size_t)(rb + ty + i) * N_NODES + c] : 0.0f;
        }
        __syncthreads();
        #pragma unroll
        for (int i = 0; i < 32; i += 8) {
            int c = cb + ty + i;
            if (c < N_NODES) g_xT[(size_t)c * NG + rb + tx] = tile[tx][ty + i];
        }
    } else {
        int e = (bid - 630) * 256 + tid;
        if (e < N_EDGES) atomicAdd(&g_deg[dst[e]], 1);
    }

    __threadfence();
    __syncthreads();
    if (tid == 0)
        sflag = (atomicAdd(&g_cnt1, 1) == gridDim.x - 1) ? 1 : 0;
    __syncthreads();
    if (!sflag) return;
    __threadfence();

    int base = tid * 8;
    int v[8];
    int run = 0;
    if (tid < 250) {
        #pragma unroll
        for (int k = 0; k < 8; k++) {
            int d = g_deg[base + k];
            v[k] = run;
            run += d;
        }
    } else {
        #pragma unroll
        for (int k = 0; k < 8; k++) v[k] = 0;
    }
    ssum[tid] = run;
    __syncthreads();
    for (int off = 1; off < 256; off <<= 1) {
        int a = (tid >= off) ? ssum[tid - off] : 0;
        __syncthreads();
        ssum[tid] += a;
        __syncthreads();
    }
    int excl = ssum[tid] - run;
    if (tid < 250) {
        #pragma unroll
        for (int k = 0; k < 8; k++) {
            g_rowptr[base + k] = excl + v[k];
            g_deg[base + k] = 0;
            g_cur[base + k] = 0;
        }
    }
    if (tid == 249) g_rowptr[N_NODES] = excl + run;
    for (int i = tid; i < NG; i += 256) g_S[i] = make_float2(0.0f, 0.0f);
    if (tid == 0) g_cnt1 = 0;
}

// =====================================================================
// K2: fused scatter + CSR-permuted w-transpose (fp16 output). [R9 exact]
// =====================================================================
__global__ void __launch_bounds__(NG) scat_wtrans_kernel(
        const float* __restrict__ win,
        const int* __restrict__ src,
        const int* __restrict__ dst) {
    __shared__ float tile[NG][33];           // [g][e], 42.2 KB
    __shared__ int s_pos[32];
    int tid = threadIdx.x;
    int eb = blockIdx.x * 32;

    if (tid < 32) {
        int e = eb + tid;
        int d = dst[e];
        int p = g_rowptr[d] + atomicAdd(&g_cur[d], 1);
        s_pos[tid] = p;
        g_srcc[p] = src[e];
    }

    #pragma unroll
    for (int r = 0; r < 8; r++) {
        int idx = r * NG + tid;
        int g = idx >> 3, q = idx & 7;
        float4 vv = *(const float4*)&win[(size_t)g * N_EDGES + eb + q * 4];
        tile[g][q * 4 + 0] = vv.x;
        tile[g][q * 4 + 1] = vv.y;
        tile[g][q * 4 + 2] = vv.z;
        tile[g][q * 4 + 3] = vv.w;
    }
    __syncthreads();

    #pragma unroll 8
    for (int e = 0; e < 32; e++) {
        g_wTh[(size_t)s_pos[e] * NG + tid] = __float2half_rn(tile[tid][e]);
    }
}

// =====================================================================
// K3: GAT reduction (blocks 0..499)  +  head composition (block 500). [R9 exact]
// =====================================================================
__global__ void __launch_bounds__(NG) gat_kernel(const float* __restrict__ W_node,
                           const float* __restrict__ W_edge,
                           const float* __restrict__ attn_l,
                           const float* __restrict__ attn_e,
                           const float* __restrict__ attn_r,
                           const float* __restrict__ fc_w,
                           const float* __restrict__ fc_b,
                           const float* __restrict__ fcc_w,
                           const float* __restrict__ fcc_b) {
    int g = threadIdx.x;

    if (blockIdx.x == N_NODES / STRIP) {
        __shared__ float s_fcw[160 * HID];   // 15 KB
        for (int i = g; i < 160 * HID; i += NG) s_fcw[i] = fc_w[i];
        __syncthreads();
        for (int idx = g; idx < 20 * HID; idx += NG) {
            int m = idx / HID, k = idx % HID;
            float acc = 0.f;
            #pragma unroll 8
            for (int q = 0; q < 160; q++)
                acc = fmaf(fcc_w[m * 160 + q], s_fcw[q * HID + k], acc);
            g_M[idx] = acc;
        }
        if (g < 20) {
            float acc = fcc_b[g];
            #pragma unroll 8
            for (int q = 0; q < 160; q++)
                acc = fmaf(fcc_w[g * 160 + q], fc_b[q], acc);
            g_bias2[g] = acc;
        }
        return;
    }

    float cL = 0.f, cE = 0.f, cR = 0.f;
    #pragma unroll
    for (int o = 0; o < OUTF; o++) {
        float wn = __ldg(&W_node[o]);
        float we = __ldg(&W_edge[o]);
        cL = fmaf(wn, __ldg(&attn_l[o]), cL);
        cR = fmaf(wn, __ldg(&attn_r[o]), cR);
        cE = fmaf(we, __ldg(&attn_e[o]), cE);
    }

    int n0 = blockIdx.x * STRIP;
    float acc1 = 0.f, acc2 = 0.f;

    #pragma unroll
    for (int nn = 0; nn < STRIP; nn++) {
        int node = n0 + nn;
        float xd = g_xT[(size_t)node * NG + g];
        float based = cR * xd;
        int s0 = g_rowptr[node], s1 = g_rowptr[node + 1];

        float den = 0.f, T1 = 0.f, T2 = 0.f;
        int j = s0;
        for (; j + 4 <= s1; j += 4) {
            int sa = g_srcc[j];
            int sb = g_srcc[j + 1];
            int sc = g_srcc[j + 2];
            int sd = g_srcc[j + 3];
            float w0 = __half2float(g_wTh[(size_t)(j    ) * NG + g]);
            float w1 = __half2float(g_wTh[(size_t)(j + 1) * NG + g]);
            float w2 = __half2float(g_wTh[(size_t)(j + 2) * NG + g]);
            float w3 = __half2float(g_wTh[(size_t)(j + 3) * NG + g]);
            float x0 = g_xT[(size_t)sa * NG + g];
            float x1 = g_xT[(size_t)sb * NG + g];
            float x2 = g_xT[(size_t)sc * NG + g];
            float x3 = g_xT[(size_t)sd * NG + g];

            float v0 = fmaf(cL, x0, fmaf(cE, w0, based));
            float v1 = fmaf(cL, x1, fmaf(cE, w1, based));
            float v2 = fmaf(cL, x2, fmaf(cE, w2, based));
            float v3 = fmaf(cL, x3, fmaf(cE, w3, based));
            v0 = fmaxf(v0, NEG_SLOPE * v0);
            v1 = fmaxf(v1, NEG_SLOPE * v1);
            v2 = fmaxf(v2, NEG_SLOPE * v2);
            v3 = fmaxf(v3, NEG_SLOPE * v3);
            float p0 = __expf(v0);
            float p1 = __expf(v1);
            float p2 = __expf(v2);
            float p3 = __expf(v3);
            den += p0; T1 = fmaf(p0, x0, T1); T2 = fmaf(p0, w0, T2);
            den += p1; T1 = fmaf(p1, x1, T1); T2 = fmaf(p1, w1, T2);
            den += p2; T1 = fmaf(p2, x2, T1); T2 = fmaf(p2, w2, T2);
            den += p3; T1 = fmaf(p3, x3, T1); T2 = fmaf(p3, w3, T2);
        }
        for (; j < s1; j++) {
            float w  = __half2float(g_wTh[(size_t)j * NG + g]);
            float xs = g_xT[(size_t)g_srcc[j] * NG + g];
            float v = fmaf(cL, xs, fmaf(cE, w, based));
            v = fmaxf(v, NEG_SLOPE * v);
            float p = __expf(v);
            den += p; T1 = fmaf(p, xs, T1); T2 = fmaf(p, w, T2);
        }
        if (s1 > s0) {
            float inv = 1.0f / den;
            acc1 = fmaf(T1, inv, acc1);
            acc2 = fmaf(T2, inv, acc2);
        }
    }
    atomicAdd(&g_S[g].x, acc1);
    atomicAdd(&g_S[g].y, acc2);
}

// =====================================================================
// K4: warp-synchronous LSTM + composed head. [R9 structure, 16 CTAs x 32]
//   ONLY change vs R9: weight preloads use float4 vector LDGs over the
//   contiguous rows (w_hh row = 24 floats @ 96B-aligned offset; g_M row
//   = 24 floats; w_ih row = 8 floats) -> 4x fewer L1tex wavefronts.
// =====================================================================
__device__ __forceinline__ float sigm(float x) { return 1.0f / (1.0f + __expf(-x)); }
__device__ __forceinline__ float tanhfast(float x) {
    float t = __expf(-2.0f * x);
    return __fdividef(1.0f - t, 1.0f + t);
}

__global__ void __launch_bounds__(32) lstm_head_kernel(
        const float* __restrict__ W_node,
        const float* __restrict__ W_edge,
        const float* __restrict__ gat_b,
        const float* __restrict__ w_ih,
        const float* __restrict__ w_hh,
        const float* __restrict__ b_ih,
        const float* __restrict__ b_hh,
        float* __restrict__ out) {
    int b = blockIdx.x;          // batch 0..15
    int lane = threadIdx.x;      // 0..31
    const float invN = 1.0f / N_NODES;

    // preload all timestep sums (lane t holds step t's pair)
    float s1 = 0.f, s2 = 0.f;
    if (lane < TT) { float2 S = g_S[b * TT + lane]; s1 = S.x; s2 = S.y; }

    // per-gate folded input coefficients + w_hh rows (lane j<24, gates i,f,g,o)
    float A1[4], A2[4], A3[4];
    float whh[4][HID];
    #pragma unroll
    for (int gg = 0; gg < 4; gg++) {
        A1[gg] = A2[gg] = A3[gg] = 0.f;
        #pragma unroll
        for (int j = 0; j < HID; j++) whh[gg][j] = 0.f;
    }
    if (lane < HID) {
        #pragma unroll
        for (int gg = 0; gg < 4; gg++) {
            int row = gg * HID + lane;
            // w_ih row: 8 floats, 32B-aligned offset -> 2 float4
            float4 wa = __ldg((const float4*)(w_ih + row * OUTF));
            float4 wb = __ldg((const float4*)(w_ih + row * OUTF + 4));
            float wv[OUTF] = {wa.x, wa.y, wa.z, wa.w, wb.x, wb.y, wb.z, wb.w};
            float a1 = 0.f, a2 = 0.f, a3 = b_ih[row] + b_hh[row];
            #pragma unroll
            for (int o = 0; o < OUTF; o++) {
                a1 = fmaf(wv[o], W_node[o], a1);
                a2 = fmaf(wv[o], W_edge[o], a2);
                a3 = fmaf(wv[o], gat_b[o], a3);
            }
            A1[gg] = a1 * invN;
            A2[gg] = a2 * invN;
            A3[gg] = a3;
            // w_hh row: 24 floats at 96B-aligned offset -> 6 float4
            const float4* wrow = (const float4*)(w_hh + row * HID);
            #pragma unroll
            for (int q = 0; q < 6; q++) {
                float4 v = __ldg(&wrow[q]);
                whh[gg][q * 4 + 0] = v.x;
                whh[gg][q * 4 + 1] = v.y;
                whh[gg][q * 4 + 2] = v.z;
                whh[gg][q * 4 + 3] = v.w;
            }
        }
    }

    // composed head row (lane m<20 -> out column m): 6 float4
    float Mrow[HID];
    #pragma unroll
    for (int j = 0; j < HID; j++) Mrow[j] = 0.f;
    float bias2 = 0.f;
    if (lane < 20) {
        const float4* mrow = (const float4*)(g_M + lane * HID);
        #pragma unroll
        for (int q = 0; q < 6; q++) {
            float4 v = mrow[q];
            Mrow[q * 4 + 0] = v.x;
            Mrow[q * 4 + 1] = v.y;
            Mrow[q * 4 + 2] = v.z;
            Mrow[q * 4 + 3] = v.w;
        }
        bias2 = g_bias2[lane];
    }

    float h = 0.f, c = 0.f, oacc = 0.f;
    for (int t = 0; t < TT; t++) {
        float S1t = __shfl_sync(0xffffffffu, s1, t);
        float S2t = __shfl_sync(0xffffffffu, s2, t);
        float g0 = fmaf(S1t, A1[0], fmaf(S2t, A2[0], A3[0]));
        float g1 = fmaf(S1t, A1[1], fmaf(S2t, A2[1], A3[1]));
        float g2 = fmaf(S1t, A1[2], fmaf(S2t, A2[2], A3[2]));
        float g3 = fmaf(S1t, A1[3], fmaf(S2t, A2[3], A3[3]));
        if (t > 0) {
            // broadcast h_{t-1}: feeds gates of step t AND output of step t-1
            #pragma unroll
            for (int j = 0; j < HID; j++) {
                float hj = __shfl_sync(0xffffffffu, h, j);
                g0 = fmaf(whh[0][j], hj, g0);
                g1 = fmaf(whh[1][j], hj, g1);
                g2 = fmaf(whh[2][j], hj, g2);
                g3 = fmaf(whh[3][j], hj, g3);
                oacc = fmaf(Mrow[j], hj, oacc);
            }
            if (lane < 20) out[(b * TT + (t - 1)) * 20 + lane] = oacc + bias2;
            oacc = 0.f;
        }
        float gi = sigm(g0);
        float gf = sigm(g1);
        float tg = tanhfast(g2);
        float go = sigm(g3);
        c = fmaf(gf, c, gi * tg);
        h = go * tanhfast(c);
    }
    // final output (step TT-1)
    #pragma unroll
    for (int j = 0; j < HID; j++) {
        float hj = __shfl_sync(0xffffffffu, h, j);
        oacc = fmaf(Mrow[j], hj, oacc);
    }
    if (lane < 20) out[(b * TT + TT - 1) * 20 + lane] = oacc + bias2;
}

// ---------------- launch ----------------
extern "C" void kernel_launch(void* const* d_in, const int* in_sizes, int n_in,
                              void* d_out, int out_size) {
    const float* x      = (const float*)d_in[0];
    const float* ew     = (const float*)d_in[1];
    const int*   src    = (const int*)  d_in[2];
    const int*   dst    = (const int*)  d_in[3];
    const float* W_node = (const float*)d_in[4];
    const float* W_edge = (const float*)d_in[5];
    const float* attn_l = (const float*)d_in[6];
    const float* attn_e = (const float*)d_in[7];
    const float* attn_r = (const float*)d_in[8];
    const float* gat_b  = (const float*)d_in[9];
    const float* w_ih   = (const float*)d_in[10];
    const float* w_hh   = (const float*)d_in[11];
    const float* b_ih   = (const float*)d_in[12];
    const float* b_hh   = (const float*)d_in[13];
    const float* fc_w   = (const float*)d_in[14];
    const float* fc_b   = (const float*)d_in[15];
    const float* fcc_w  = (const float*)d_in[16];
    const float* fcc_b  = (const float*)d_in[17];
    float* out = (float*)d_out;

    xtrans_hist_scan_kernel<<<755, 256>>>(x, dst);
    scat_wtrans_kernel<<<N_EDGES / 32, NG>>>(ew, src, dst);
    gat_kernel<<<N_NODES / STRIP + 1, NG>>>(W_node, W_edge, attn_l, attn_e, attn_r,
                                            fc_w, fc_b, fcc_w, fcc_b);
    lstm_head_kernel<<<BB, 32>>>(W_node, W_edge, gat_b, w_ih, w_hh, b_ih, b_hh, out);
}